// round 5
// baseline (speedup 1.0000x reference)
#include <cuda_runtime.h>
#include <math.h>

namespace {

constexpr int B  = 128;
constexpr int P  = 196;
constexpr int DE = 2048;   // DENC
constexpr int DD = 512;    // DDEC
constexpr int DA = 512;    // DATT
constexpr int DM = 512;    // DEMB
constexpr int V  = 10000;
constexpr int L  = 21;
constexpr int T  = 20;
constexpr int XK = DM + DE + DD;  // 3072
constexpr int G4 = 4 * DD;        // 2048
constexpr int KS_G = 8;           // K-split: lstm gemm (3072/8 = 384)
constexpr int KS_H = 4;           // K-split: attn2+gate gemm (512/4 = 128)
constexpr int KS_0 = 8;           // K-split: h0/c0 (2048/8 = 256)

constexpr long long OFF_PRED   = 0;
constexpr long long OFF_ALPHA  = (long long)B * T * V;
constexpr long long OFF_CAPS   = OFF_ALPHA + (long long)B * T * P;
constexpr long long OFF_DECLEN = OFF_CAPS + (long long)B * L;
constexpr long long OFF_SORT   = OFF_DECLEN + B;

// ---------------- scratch ----------------------------------------------------
__device__ int g_sort[B];
__device__ int g_declen[B];
__device__ int g_caps[B * L];
__device__ __align__(16) float g_enc[(size_t)B * P * DE];
__device__ __align__(16) float g_attn1[(size_t)B * P * DA];
__device__ __align__(16) float g_mean[B * DE];
__device__ __align__(16) float g_h[B * DD];
__device__ __align__(16) float g_c[B * DD];
__device__ __align__(16) float g_hnew[B * DD];
__device__ __align__(16) float g_attn2p[KS_H * B * DA];
__device__ __align__(16) float g_gatep[KS_H * B * DE];
__device__ __align__(16) float g_alpha[B * P];
__device__ __align__(16) float g_e[B * P];
__device__ __align__(16) float g_x[B * XK];
__device__ __align__(16) float g_gp[(size_t)KS_G * B * G4];   // also reused for h0/c0 parts
__device__ __align__(16) float g_Wg[(size_t)XK * G4];

__device__ __forceinline__ float sigm(float x) { return 1.f / (1.f + expf(-x)); }

// ---------------- sort: stable argsort(-lengths) -----------------------------
__global__ void k_sort(const int* __restrict__ cap_len,
                       const int* __restrict__ caps_in,
                       float* __restrict__ out) {
    __shared__ int len[B];
    int i = threadIdx.x;
    len[i] = cap_len[i];
    __syncthreads();
    int li = len[i];
    int pos = 0;
    for (int j = 0; j < B; j++) {
        int lj = len[j];
        pos += (lj > li) || (lj == li && j < i);
    }
    g_sort[pos]   = i;
    g_declen[pos] = li - 1;
    out[OFF_SORT + pos]   = (float)i;
    out[OFF_DECLEN + pos] = (float)(li - 1);
    __syncthreads();
    int src = g_sort[i];
    for (int l = 0; l < L; l++) {
        int tok = caps_in[src * L + l];
        g_caps[i * L + l] = tok;
        out[OFF_CAPS + (long long)i * L + l] = (float)tok;
    }
}

// ---------------- gather enc into sorted order -------------------------------
__global__ void k_gather(const float* __restrict__ enc) {
    int b = blockIdx.y;
    size_t off = (size_t)blockIdx.x * 1024 + (size_t)threadIdx.x * 4;
    const float4* src = (const float4*)(enc + (size_t)g_sort[b] * P * DE + off);
    float4* dst = (float4*)(g_enc + (size_t)b * P * DE + off);
    *dst = *src;
}

// ---------------- build combined [W_ih; W_hh] --------------------------------
__global__ void k_copyWg(const float* __restrict__ W_ih,
                         const float* __restrict__ W_hh) {
    size_t i = (size_t)blockIdx.x * blockDim.x + threadIdx.x;
    size_t n1 = (size_t)(DM + DE) * G4;
    size_t tot = (size_t)XK * G4;
    if (i >= tot) return;
    g_Wg[i] = (i < n1) ? W_ih[i] : W_hh[i - n1];
}

// ---------------- mean over P ------------------------------------------------
__global__ void k_mean() {
    int b = blockIdx.y;
    int d = blockIdx.x * 256 + threadIdx.x;
    const float* e = g_enc + (size_t)b * P * DE + d;
    float s = 0.f;
#pragma unroll 4
    for (int p = 0; p < P; p++) s += e[(size_t)p * DE];
    g_mean[b * DE + d] = s * (1.0f / (float)P);
}

// ---------------- GEMM core: 64x128 tile, BK=16, 256 thr, 4x8 per thread -----
constexpr int BM = 64, BN = 128, BK = 16;

__device__ __forceinline__ void core(const float* __restrict__ A,
                                     const float* __restrict__ Bm,
                                     int N, int K, int m0, int n0,
                                     int k0, int kend,
                                     float (&acc)[4][8], float* sA, float* sB) {
    int tid = threadIdx.x;
    int arow = tid >> 2, ak = (tid & 3) << 2;    // A: 64 rows x 16 k, 1 float4/thr
    int brow = tid >> 4, bc = (tid & 15) << 3;   // B: 16 k x 128 n, 8 floats/thr
    int ty = tid >> 4, tx = tid & 15;
    int col = n0 + bc;
    for (int kt = k0; kt < kend; kt += BK) {
        // load A row-major [m][k]
        *(float4*)(sA + arow * BK + ak) =
            *(const float4*)(A + (size_t)(m0 + arow) * K + kt + ak);
        const float* bp = Bm + (size_t)(kt + brow) * N + col;
        if (col + 7 < N) {
            *(float4*)(sB + brow * BN + bc)     = *(const float4*)bp;
            *(float4*)(sB + brow * BN + bc + 4) = *(const float4*)(bp + 4);
        } else {
#pragma unroll
            for (int j = 0; j < 8; j++)
                sB[brow * BN + bc + j] = (col + j < N) ? bp[j] : 0.f;
        }
        __syncthreads();
#pragma unroll
        for (int kk = 0; kk < BK; kk++) {
            float a0 = sA[(ty * 4 + 0) * BK + kk];
            float a1 = sA[(ty * 4 + 1) * BK + kk];
            float a2 = sA[(ty * 4 + 2) * BK + kk];
            float a3 = sA[(ty * 4 + 3) * BK + kk];
            float4 b0 = *(const float4*)(sB + kk * BN + tx * 8);
            float4 b1 = *(const float4*)(sB + kk * BN + tx * 8 + 4);
            float bv[8] = {b0.x, b0.y, b0.z, b0.w, b1.x, b1.y, b1.z, b1.w};
#pragma unroll
            for (int j = 0; j < 8; j++) {
                acc[0][j] += a0 * bv[j];
                acc[1][j] += a1 * bv[j];
                acc[2][j] += a2 * bv[j];
                acc[3][j] += a3 * bv[j];
            }
        }
        __syncthreads();
    }
}

// C = A@B + bias (full K), no skip — used for attn1
__global__ void k_gemm_bias(const float* __restrict__ A, const float* __restrict__ Bm,
                            const float* __restrict__ bias, float* __restrict__ C,
                            int N, int K) {
    __shared__ float sA[BM * BK];
    __shared__ float sB[BK * BN];
    float acc[4][8] = {};
    int m0 = blockIdx.y * BM, n0 = blockIdx.x * BN;
    core(A, Bm, N, K, m0, n0, 0, K, acc, sA, sB);
    int ty = threadIdx.x >> 4, tx = threadIdx.x & 15;
    int col = n0 + tx * 8;
    float bv[8];
#pragma unroll
    for (int j = 0; j < 8; j++) bv[j] = bias[col + j];
#pragma unroll
    for (int i = 0; i < 4; i++) {
        float* cp = C + (size_t)(m0 + ty * 4 + i) * N + col;
        *(float4*)cp       = make_float4(acc[i][0] + bv[0], acc[i][1] + bv[1],
                                         acc[i][2] + bv[2], acc[i][3] + bv[3]);
        *(float4*)(cp + 4) = make_float4(acc[i][4] + bv[4], acc[i][5] + bv[5],
                                         acc[i][6] + bv[6], acc[i][7] + bv[7]);
    }
}

// part[z] = A@B over K-chunk z (grid.z = KSPLIT); tile-skip via t (t<0 = none)
__global__ void k_gemm_part(const float* __restrict__ A, const float* __restrict__ Bm,
                            float* __restrict__ part, int N, int K, int t) {
    int m0 = blockIdx.y * BM;
    if (t >= 0 && t >= g_declen[m0]) return;   // sorted: first row most active
    __shared__ float sA[BM * BK];
    __shared__ float sB[BK * BN];
    float acc[4][8] = {};
    int n0 = blockIdx.x * BN;
    int kl = K / gridDim.z;
    core(A, Bm, N, K, m0, n0, blockIdx.z * kl, (blockIdx.z + 1) * kl, acc, sA, sB);
    int ty = threadIdx.x >> 4, tx = threadIdx.x & 15;
    float* Cz = part + (size_t)blockIdx.z * B * N;
#pragma unroll
    for (int i = 0; i < 4; i++) {
        float* cp = Cz + (size_t)(m0 + ty * 4 + i) * N + n0 + tx * 8;
        *(float4*)cp       = make_float4(acc[i][0], acc[i][1], acc[i][2], acc[i][3]);
        *(float4*)(cp + 4) = make_float4(acc[i][4], acc[i][5], acc[i][6], acc[i][7]);
    }
}

// combined attn2 (N=512) + gate (N=2048) partial GEMMs, A = h, K = DD
__global__ void k_gemm_hW(const float* __restrict__ Wda,
                          const float* __restrict__ Wbeta, int t) {
    int m0 = blockIdx.y * BM;
    if (t >= g_declen[m0]) return;
    __shared__ float sA[BM * BK];
    __shared__ float sB[BK * BN];
    float acc[4][8] = {};
    const float* Bm;
    float* outp;
    int N, n0;
    if (blockIdx.x < DA / BN) {
        Bm = Wda;  N = DA; n0 = blockIdx.x * BN;
        outp = g_attn2p + (size_t)blockIdx.z * B * DA;
    } else {
        Bm = Wbeta; N = DE; n0 = (blockIdx.x - DA / BN) * BN;
        outp = g_gatep + (size_t)blockIdx.z * B * DE;
    }
    int kl = DD / KS_H;
    core(g_h, Bm, N, DD, m0, n0, blockIdx.z * kl, (blockIdx.z + 1) * kl, acc, sA, sB);
    int ty = threadIdx.x >> 4, tx = threadIdx.x & 15;
#pragma unroll
    for (int i = 0; i < 4; i++) {
        float* cp = outp + (size_t)(m0 + ty * 4 + i) * N + n0 + tx * 8;
        *(float4*)cp       = make_float4(acc[i][0], acc[i][1], acc[i][2], acc[i][3]);
        *(float4*)(cp + 4) = make_float4(acc[i][4], acc[i][5], acc[i][6], acc[i][7]);
    }
}

// preds = hnew@W_fc + b_fc, masked; inactive tiles fast-zero
__global__ void k_gemm_preds(const float* __restrict__ Bm,
                             const float* __restrict__ bias,
                             float* __restrict__ out, int t) {
    int m0 = blockIdx.y * BM, n0 = blockIdx.x * BN;
    int ty = threadIdx.x >> 4, tx = threadIdx.x & 15;
    int col = n0 + tx * 8;
    if (t >= g_declen[m0]) {
#pragma unroll
        for (int i = 0; i < 4; i++) {
            int b = m0 + ty * 4 + i;
            float* op = out + OFF_PRED + (size_t)b * T * V + (size_t)t * V;
#pragma unroll
            for (int j = 0; j < 8; j++)
                if (col + j < V) op[col + j] = 0.f;
        }
        return;
    }
    __shared__ float sA[BM * BK];
    __shared__ float sB[BK * BN];
    float acc[4][8] = {};
    core(g_hnew, Bm, V, DD, m0, n0, 0, DD, acc, sA, sB);
#pragma unroll
    for (int i = 0; i < 4; i++) {
        int b = m0 + ty * 4 + i;
        int act = (t < g_declen[b]);
        float* op = out + OFF_PRED + (size_t)b * T * V + (size_t)t * V;
#pragma unroll
        for (int j = 0; j < 8; j++) {
            int c = col + j;
            if (c < V) op[c] = act ? (acc[i][j] + bias[c]) : 0.f;
        }
    }
}

// e[b,p] = sum_k relu(attn1 + sum_z attn2p[z] + b_da) * w_f + b_f
__global__ void k_e(const float* __restrict__ b_da,
                    const float* __restrict__ wf, const float* __restrict__ bf,
                    int t) {
    int bp = blockIdx.x;
    int b = bp / P;
    if (t >= g_declen[b]) return;
    int tid = threadIdx.x;  // 128
    const float* a1 = g_attn1 + (size_t)bp * DA;
    float s = 0.f;
#pragma unroll 2
    for (int k = tid; k < DA; k += 128) {
        float v = a1[k] + b_da[k];
#pragma unroll
        for (int z = 0; z < KS_H; z++) v += g_attn2p[(z * B + b) * DA + k];
        s += fmaxf(v, 0.f) * wf[k];
    }
    __shared__ float red[128];
    red[tid] = s;
    __syncthreads();
    for (int st = 64; st > 0; st >>= 1) {
        if (tid < st) red[tid] += red[tid + st];
        __syncthreads();
    }
    if (tid == 0) g_e[bp] = red[0] + bf[0];
}

// softmax over P; inactive -> zero output row
__global__ void k_softmax(float* __restrict__ out, int t) {
    int b = blockIdx.x;
    int tid = threadIdx.x;  // 256
    float* op = out + OFF_ALPHA + (size_t)b * T * P + (size_t)t * P;
    if (t >= g_declen[b]) {
        if (tid < P) op[tid] = 0.f;
        return;
    }
    __shared__ float red[256];
    float v = (tid < P) ? g_e[b * P + tid] : -1e30f;
    red[tid] = v;
    __syncthreads();
    for (int st = 128; st > 0; st >>= 1) {
        if (tid < st) red[tid] = fmaxf(red[tid], red[tid + st]);
        __syncthreads();
    }
    float mx = red[0];
    __syncthreads();
    float ex = (tid < P) ? expf(v - mx) : 0.f;
    red[tid] = ex;
    __syncthreads();
    for (int st = 128; st > 0; st >>= 1) {
        if (tid < st) red[tid] += red[tid + st];
        __syncthreads();
    }
    float inv = 1.f / red[0];
    if (tid < P) {
        float a = ex * inv;
        g_alpha[b * P + tid] = a;
        op[tid] = a;
    }
}

// build x = [emb | gate*ctx | h] in one kernel; grid (12, B)
__global__ void k_x(const float* __restrict__ emb, const float* __restrict__ b_beta,
                    int t) {
    int b = blockIdx.y;
    if (t >= g_declen[b]) return;
    int i = blockIdx.x * 256 + threadIdx.x;  // 0..3071
    if (i < DM) {
        int tok = g_caps[b * L + t];
        g_x[(size_t)b * XK + i] = emb[(size_t)tok * DM + i];
    } else if (i < DM + DE) {
        __shared__ float sa[P];
        for (int k = threadIdx.x; k < P; k += 256) sa[k] = g_alpha[b * P + k];
        __syncthreads();
        int d = i - DM;
        const float* e = g_enc + (size_t)b * P * DE + d;
        float s = 0.f;
#pragma unroll 4
        for (int p = 0; p < P; p++) s += e[(size_t)p * DE] * sa[p];
        float gt = b_beta[d];
#pragma unroll
        for (int z = 0; z < KS_H; z++) gt += g_gatep[(size_t)(z * B + b) * DE + d];
        g_x[(size_t)b * XK + i] = sigm(gt) * s;
    } else {
        int j = i - DM - DE;
        g_x[(size_t)b * XK + i] = g_h[b * DD + j];
    }
}

// LSTM cell: reduce KS_G partials + biases, nonlinearity, state update
__global__ void k_lstm(const float* __restrict__ b_ih, const float* __restrict__ b_hh,
                       int t) {
    int idx = blockIdx.x * blockDim.x + threadIdx.x;  // B*DD
    int b = idx >> 9, j = idx & 511;
    if (t >= g_declen[b]) return;
    float gi = b_ih[j] + b_hh[j];
    float gf = b_ih[DD + j] + b_hh[DD + j];
    float gg = b_ih[2 * DD + j] + b_hh[2 * DD + j];
    float go = b_ih[3 * DD + j] + b_hh[3 * DD + j];
#pragma unroll
    for (int z = 0; z < KS_G; z++) {
        const float* gp = g_gp + ((size_t)z * B + b) * G4;
        gi += gp[j];
        gf += gp[DD + j];
        gg += gp[2 * DD + j];
        go += gp[3 * DD + j];
    }
    float cn = sigm(gf) * g_c[idx] + sigm(gi) * tanhf(gg);
    float hn = sigm(go) * tanhf(cn);
    g_hnew[idx] = hn;
    g_h[idx] = hn;
    g_c[idx] = cn;
}

// h0/c0: reduce KS_0 partials + bias
__global__ void k_red_hc(const float* __restrict__ b_hd, const float* __restrict__ b_cd) {
    int idx = blockIdx.x * blockDim.x + threadIdx.x;  // B*DD
    int b = idx >> 9, j = idx & 511;
    float h = b_hd[j], c = b_cd[j];
    const float* php = g_gp;
    const float* pcp = g_gp + (size_t)KS_0 * B * DD;
#pragma unroll
    for (int z = 0; z < KS_0; z++) {
        h += php[((size_t)z * B + b) * DD + j];
        c += pcp[((size_t)z * B + b) * DD + j];
    }
    g_h[idx] = h;
    g_c[idx] = c;
    g_hnew[idx] = h;
}

}  // namespace

extern "C" void kernel_launch(void* const* d_in, const int* in_sizes, int n_in,
                              void* d_out, int out_size) {
    const float* enc    = (const float*)d_in[0];
    const int*   caps   = (const int*)d_in[1];
    const int*   clen   = (const int*)d_in[2];
    const float* W_ea   = (const float*)d_in[3];
    const float* b_ea   = (const float*)d_in[4];
    const float* W_da   = (const float*)d_in[5];
    const float* b_da   = (const float*)d_in[6];
    const float* w_f    = (const float*)d_in[7];
    const float* b_f    = (const float*)d_in[8];
    const float* emb    = (const float*)d_in[9];
    const float* W_ih   = (const float*)d_in[10];
    const float* b_ih   = (const float*)d_in[11];
    const float* W_hh   = (const float*)d_in[12];
    const float* b_hh   = (const float*)d_in[13];
    const float* W_hd   = (const float*)d_in[14];
    const float* b_hd   = (const float*)d_in[15];
    const float* W_cd   = (const float*)d_in[16];
    const float* b_cd   = (const float*)d_in[17];
    const float* W_beta = (const float*)d_in[18];
    const float* b_beta = (const float*)d_in[19];
    const float* W_fc   = (const float*)d_in[20];
    const float* b_fc   = (const float*)d_in[21];
    float* out = (float*)d_out;

    float *p_enc, *p_attn1, *p_mean, *p_x, *p_gp, *p_Wg;
    cudaGetSymbolAddress((void**)&p_enc, g_enc);
    cudaGetSymbolAddress((void**)&p_attn1, g_attn1);
    cudaGetSymbolAddress((void**)&p_mean, g_mean);
    cudaGetSymbolAddress((void**)&p_x, g_x);
    cudaGetSymbolAddress((void**)&p_gp, g_gp);
    cudaGetSymbolAddress((void**)&p_Wg, g_Wg);

    // ---- setup ----
    k_sort<<<1, B>>>(clen, caps, out);
    k_gather<<<dim3(P * DE / 1024, B), 256>>>(enc);
    {
        size_t tot = (size_t)XK * G4;
        k_copyWg<<<(unsigned)((tot + 1023) / 1024), 1024>>>(W_ih, W_hh);
    }
    k_mean<<<dim3(DE / 256, B), 256>>>();
    // h0/c0 partials (K-split x8) then reduce
    k_gemm_part<<<dim3(DD / BN, B / BM, KS_0), 256>>>(p_mean, W_hd, p_gp, DD, DE, -1);
    k_gemm_part<<<dim3(DD / BN, B / BM, KS_0), 256>>>(p_mean, W_cd,
                                                      p_gp + (size_t)KS_0 * B * DD,
                                                      DD, DE, -1);
    k_red_hc<<<B * DD / 256, 256>>>(b_hd, b_cd);
    // attn1 = enc_sorted @ W_ea + b_ea   (M = 25088)
    k_gemm_bias<<<dim3(DA / BN, (B * P) / BM), 256>>>(p_enc, W_ea, b_ea, p_attn1, DA, DE);

    // ---- time loop ----
    for (int t = 0; t < T; t++) {
        k_gemm_hW<<<dim3(DA / BN + DE / BN, B / BM, KS_H), 256>>>(W_da, W_beta, t);
        k_e<<<B * P, 128>>>(b_da, w_f, b_f, t);
        k_softmax<<<B, 256>>>(out, t);
        k_x<<<dim3(XK / 256, B), 256>>>(emb, b_beta, t);
        k_gemm_part<<<dim3(G4 / BN, B / BM, KS_G), 256>>>(p_x, p_Wg, p_gp, G4, XK, t);
        k_lstm<<<B * DD / 256, 256>>>(b_ih, b_hh, t);
        k_gemm_preds<<<dim3((V + BN - 1) / BN, B / BM), 256>>>(W_fc, b_fc, out, t);
    }
}